// round 1
// baseline (speedup 1.0000x reference)
#include <cuda_runtime.h>
#include <cuda_bf16.h>

// ---------------------------------------------------------------------------
// StyleLayer: modulated conv2d (StyleGAN2), B=8, CIN=COUT=512, K=3, RES=64
// Strategy:
//   style  = w @ (affine_w * AFF_SCALE)^T + affine_b            [8,512]
//   wsq    = sum_k conv_w^2                                      [512,512]
//   dcoef  = CONV_SCALE * rsqrt(CONV_SCALE^2 * sum_c style^2*wsq + 1e-8)
//   xs_pad = zero-padded (66x66) x * style                       [8,512,66,66]
//   y      = dcoef * conv(xs_pad, conv_w)  -> +noise -> lrelu*sqrt2
// Main conv = per-sample implicit GEMM M=512 N=4096 K=4608, FP32 via fma.rn.f32x2
// ---------------------------------------------------------------------------

#define B_      8
#define CIN_    512
#define COUT_   512
#define SDIM_   512
#define RES_    64
#define NPIX_   4096          // 64*64
#define KDIM_   4608          // 512*9
#define PADW_   66
#define PADA_   4356          // 66*66
#define AFF_SCALE   0.044194173824159216f   // 1/sqrt(512)
#define CONV_SCALE  0.014731391274719739f   // 1/sqrt(4608)
#define LRELU_GAIN  1.4142135623730951f

// scratch (allocation-free rules: __device__ globals)
__device__ __align__(16) static float g_xs[B_ * CIN_ * PADA_];   // ~71 MB
__device__ static float g_style[B_ * CIN_];
__device__ static float g_wsq[COUT_ * CIN_];
__device__ static float g_dcoef[B_ * COUT_];

// packed fp32x2 fma: d = a*b + d
__device__ __forceinline__ void ffma2(unsigned long long& d,
                                      unsigned long long a,
                                      unsigned long long b) {
    asm("fma.rn.f32x2 %0, %1, %2, %0;" : "+l"(d) : "l"(a), "l"(b));
}

// ---------------- prep kernels ----------------

__global__ void prep_style(const float* __restrict__ w,
                           const float* __restrict__ affine_w,
                           const float* __restrict__ affine_b) {
    __shared__ float ws[SDIM_];
    const int b = blockIdx.x;
    const int c = threadIdx.x;
    ws[c] = w[b * SDIM_ + c];
    __syncthreads();
    const float* ar = affine_w + c * SDIM_;
    float s = 0.f;
    #pragma unroll 8
    for (int k = 0; k < SDIM_; ++k) s += ws[k] * ar[k];
    g_style[b * CIN_ + c] = s * AFF_SCALE + affine_b[c];
}

__global__ void prep_wsq(const float* __restrict__ conv_w) {
    const int idx = blockIdx.x * blockDim.x + threadIdx.x;   // o*512+c
    if (idx >= COUT_ * CIN_) return;
    const float* p = conv_w + idx * 9;
    float s = 0.f;
    #pragma unroll
    for (int t = 0; t < 9; ++t) s += p[t] * p[t];
    g_wsq[idx] = s;
}

__global__ void prep_dcoef() {
    __shared__ float s2[CIN_];
    const int b = blockIdx.x;
    const int o = threadIdx.x;
    const float st = g_style[b * CIN_ + o];
    s2[o] = st * st;
    __syncthreads();
    const float* wr = g_wsq + o * CIN_;
    float s = 0.f;
    #pragma unroll 8
    for (int c = 0; c < CIN_; ++c) s += s2[c] * wr[c];
    const float d = rsqrtf(CONV_SCALE * CONV_SCALE * s + 1e-8f);
    g_dcoef[b * COUT_ + o] = CONV_SCALE * d;
}

__global__ void prep_xs(const float* __restrict__ x) {
    const int idx = blockIdx.x * blockDim.x + threadIdx.x;   // full padded index
    const int bc = idx / PADA_;           // b*512+c
    const int p  = idx - bc * PADA_;
    const int py = p / PADW_;
    const int px = p - py * PADW_;
    float v = 0.f;
    if (py >= 1 && py <= RES_ && px >= 1 && px <= RES_) {
        const int b = bc >> 9;
        v = x[(bc * RES_ + (py - 1)) * RES_ + (px - 1)] * g_style[bc];
        (void)b;
    }
    g_xs[idx] = v;
}

// ---------------- main conv: implicit GEMM 128x128x8, FFMA2 ----------------
// grid (32, 4, 8): N-tiles(pixels), M-tiles(cout), sample

__global__ __launch_bounds__(256, 2)
void conv_main(const float* __restrict__ conv_w,
               const float* __restrict__ noise,
               const float* __restrict__ nscale,
               const float* __restrict__ bias,
               float* __restrict__ out) {
    __shared__ __align__(16) float2 As[2][8][128];     // duplicated weights (w,w)
    __shared__ __align__(16) float  Bs[2][8][132];     // im2col'd pixels (+pad)

    const int tid = threadIdx.x;
    const int tx = tid & 15;          // pixel group 0..15
    const int ty = tid >> 4;          // cout group  0..15
    const int n0 = blockIdx.x * 128;
    const int m0 = blockIdx.y * 128;
    const int b  = blockIdx.z;

    // A staging: each thread loads float4 of conv_w row
    const int am  = tid >> 1;                 // 0..127 cout within tile
    const int akq = (tid & 1) * 4;            // k offset 0 or 4
    const float* aPtr = conv_w + (size_t)(m0 + am) * KDIM_ + akq;

    // B staging: each thread loads 4 consecutive pixels for one k-row
    const int bkt = tid >> 5;                 // 0..7 k within chunk
    const int jb  = (tid & 31) * 4;           // 0..124 pixel within tile
    const int py  = (n0 + jb) >> 6;           // image row
    const int px  = (n0 + jb) & 63;           // image col (multiple of 4)
    const float* xsBase = g_xs + (size_t)b * (CIN_ * PADA_);

    unsigned long long acc[8][4];
    #pragma unroll
    for (int i = 0; i < 8; ++i)
        #pragma unroll
        for (int j = 0; j < 4; ++j) acc[i][j] = 0ull;

    // ---- preload chunk 0 ----
    {
        float4 a = *reinterpret_cast<const float4*>(aPtr);
        const int k = bkt;
        const int c = k / 9, t = k - 9 * c, r = t / 3, s = t - 3 * r;
        const float* bp = xsBase + c * PADA_ + (py + r) * PADW_ + (px + s);
        As[0][akq + 0][am] = make_float2(a.x, a.x);
        As[0][akq + 1][am] = make_float2(a.y, a.y);
        As[0][akq + 2][am] = make_float2(a.z, a.z);
        As[0][akq + 3][am] = make_float2(a.w, a.w);
        Bs[0][bkt][jb + 0] = bp[0];
        Bs[0][bkt][jb + 1] = bp[1];
        Bs[0][bkt][jb + 2] = bp[2];
        Bs[0][bkt][jb + 3] = bp[3];
    }
    __syncthreads();

    const int NCHUNK = KDIM_ / 8;   // 576
    int p = 0;
    for (int ch = 0; ch < NCHUNK; ++ch) {
        float4 a;
        float bv0 = 0.f, bv1 = 0.f, bv2 = 0.f, bv3 = 0.f;
        const bool more = (ch + 1 < NCHUNK);
        if (more) {
            a = *reinterpret_cast<const float4*>(aPtr + (ch + 1) * 8);
            const int k = (ch + 1) * 8 + bkt;
            const int c = k / 9, t = k - 9 * c, r = t / 3, s = t - 3 * r;
            const float* bp = xsBase + c * PADA_ + (py + r) * PADW_ + (px + s);
            bv0 = bp[0]; bv1 = bp[1]; bv2 = bp[2]; bv3 = bp[3];
        }

        #pragma unroll
        for (int k = 0; k < 8; ++k) {
            const ulonglong2* a2 =
                reinterpret_cast<const ulonglong2*>(&As[p][k][0]) + ty * 4;
            const float* brow = &Bs[p][k][0] + tx * 8;
            const ulonglong2 xa = *reinterpret_cast<const ulonglong2*>(brow);
            const ulonglong2 xb = *reinterpret_cast<const ulonglong2*>(brow + 4);
            const ulonglong2 wA = a2[0], wB = a2[1], wC = a2[2], wD = a2[3];
            const unsigned long long wv[8] = {wA.x, wA.y, wB.x, wB.y,
                                              wC.x, wC.y, wD.x, wD.y};
            #pragma unroll
            for (int i = 0; i < 8; ++i) {
                ffma2(acc[i][0], wv[i], xa.x);
                ffma2(acc[i][1], wv[i], xa.y);
                ffma2(acc[i][2], wv[i], xb.x);
                ffma2(acc[i][3], wv[i], xb.y);
            }
        }

        if (more) {
            const int q = p ^ 1;
            As[q][akq + 0][am] = make_float2(a.x, a.x);
            As[q][akq + 1][am] = make_float2(a.y, a.y);
            As[q][akq + 2][am] = make_float2(a.z, a.z);
            As[q][akq + 3][am] = make_float2(a.w, a.w);
            Bs[q][bkt][jb + 0] = bv0;
            Bs[q][bkt][jb + 1] = bv1;
            Bs[q][bkt][jb + 2] = bv2;
            Bs[q][bkt][jb + 3] = bv3;
        }
        __syncthreads();
        p ^= 1;
    }

    // ---- epilogue: dcoef, noise, bias, lrelu*sqrt2 ----
    const float ns = nscale[0];
    float nz[8];
    #pragma unroll
    for (int j = 0; j < 8; ++j)
        nz[j] = noise[b * NPIX_ + n0 + tx * 8 + j] * ns;

    #pragma unroll
    for (int i = 0; i < 8; ++i) {
        const int row = m0 + ty * 8 + i;
        const float dc = g_dcoef[b * COUT_ + row];
        const float bi = bias[row];
        float* orow = out + ((size_t)b * COUT_ + row) * NPIX_ + n0 + tx * 8;
        float4 o0, o1;
        float res[8];
        #pragma unroll
        for (int jp = 0; jp < 4; ++jp) {
            const float2 v = *reinterpret_cast<const float2*>(&acc[i][jp]);
            float t0 = v.x * dc + nz[jp * 2 + 0] + bi;
            float t1 = v.y * dc + nz[jp * 2 + 1] + bi;
            res[jp * 2 + 0] = (t0 > 0.f) ? t0 * LRELU_GAIN : t0 * (0.2f * LRELU_GAIN);
            res[jp * 2 + 1] = (t1 > 0.f) ? t1 * LRELU_GAIN : t1 * (0.2f * LRELU_GAIN);
        }
        o0 = make_float4(res[0], res[1], res[2], res[3]);
        o1 = make_float4(res[4], res[5], res[6], res[7]);
        reinterpret_cast<float4*>(orow)[0] = o0;
        reinterpret_cast<float4*>(orow)[1] = o1;
    }
}

// ---------------- launch ----------------

extern "C" void kernel_launch(void* const* d_in, const int* in_sizes, int n_in,
                              void* d_out, int out_size) {
    const float* x        = (const float*)d_in[0];
    const float* w        = (const float*)d_in[1];
    const float* noise    = (const float*)d_in[2];
    const float* affine_w = (const float*)d_in[3];
    const float* affine_b = (const float*)d_in[4];
    const float* conv_w   = (const float*)d_in[5];
    const float* nscale   = (const float*)d_in[6];
    const float* bias     = (const float*)d_in[7];
    float* out = (float*)d_out;

    prep_style<<<B_, SDIM_>>>(w, affine_w, affine_b);
    prep_wsq<<<(COUT_ * CIN_) / 256, 256>>>(conv_w);
    prep_dcoef<<<B_, COUT_>>>();
    prep_xs<<<(B_ * CIN_ * PADA_) / 256, 256>>>(x);
    conv_main<<<dim3(32, 4, B_), 256>>>(conv_w, noise, nscale, bias, out);
}

// round 5
// speedup vs baseline: 3.1504x; 3.1504x over previous
#include <cuda_runtime.h>
#include <cuda_bf16.h>
#include <cstdint>
#include <cstddef>

// ---------------------------------------------------------------------------
// StyleLayer via mma.sync bf16 hi/lo (3-pass), static 48KB smem, no host APIs.
//   style  = w @ (affine_w*AFF_SCALE)^T + affine_b
//   dcoef  = CONV_SCALE * rsqrt(CONV_SCALE^2 * sum_c style^2*wsq + 1e-8)
//   planes: plane[b][c][s][y][px] = pad(x*style)[b,c,y,px+s]  (bf16 hi+lo)
//   W[o][k'=t*512+c] = conv_w[o][c][t]                         (bf16 hi+lo)
//   D = Wh*Ph + Wl*Ph + Wh*Pl   (fp32 accum; omits only lo*lo)
//   epilogue: *dcoef + noise*ns + bias -> lrelu*sqrt2
// GEMM per sample: M=512, N=4096, K=4608.
// CTA tile 128x64, K-chunk 32, 2-stage cp.async, 8 warps (4M x 2N, 32x32).
// ---------------------------------------------------------------------------

#define B_      8
#define CIN_    512
#define COUT_   512
#define SDIM_   512
#define NPIX_   4096
#define KDIM_   4608
#define AFF_SCALE   0.044194173824159216f
#define CONV_SCALE  0.014731391274719739f
#define LRELU_GAIN  1.4142135623730951f

#define PLANE_ELEMS ((size_t)B_ * CIN_ * 3 * 66 * 64)
__device__ __align__(16) static __nv_bfloat16 g_bh[PLANE_ELEMS];
__device__ __align__(16) static __nv_bfloat16 g_bl[PLANE_ELEMS];
__device__ __align__(16) static __nv_bfloat16 g_wh[COUT_ * KDIM_];
__device__ __align__(16) static __nv_bfloat16 g_wl[COUT_ * KDIM_];
__device__ static float g_style[B_ * CIN_];
__device__ static float g_wsq[COUT_ * CIN_];
__device__ static float g_dcoef[B_ * COUT_];

// ---------------- prep kernels ----------------

__global__ void prep_style(const float* __restrict__ w,
                           const float* __restrict__ affine_w,
                           const float* __restrict__ affine_b) {
    __shared__ float ws[SDIM_];
    const int b = blockIdx.x, c = threadIdx.x;
    ws[c] = w[b * SDIM_ + c];
    __syncthreads();
    const float* ar = affine_w + c * SDIM_;
    float s = 0.f;
    #pragma unroll 8
    for (int k = 0; k < SDIM_; ++k) s += ws[k] * ar[k];
    g_style[b * CIN_ + c] = s * AFF_SCALE + affine_b[c];
}

__global__ void prep_wsq(const float* __restrict__ conv_w) {
    const int idx = blockIdx.x * blockDim.x + threadIdx.x;
    if (idx >= COUT_ * CIN_) return;
    const float* p = conv_w + idx * 9;
    float s = 0.f;
    #pragma unroll
    for (int t = 0; t < 9; ++t) s += p[t] * p[t];
    g_wsq[idx] = s;
}

__global__ void prep_dcoef() {
    __shared__ float s2[CIN_];
    const int b = blockIdx.x, o = threadIdx.x;
    const float st = g_style[b * CIN_ + o];
    s2[o] = st * st;
    __syncthreads();
    const float* wr = g_wsq + o * CIN_;
    float s = 0.f;
    #pragma unroll 8
    for (int c = 0; c < CIN_; ++c) s += s2[c] * wr[c];
    g_dcoef[b * COUT_ + o] =
        CONV_SCALE * rsqrtf(CONV_SCALE * CONV_SCALE * s + 1e-8f);
}

__global__ void prep_wsplit(const float* __restrict__ conv_w) {
    const int idx = blockIdx.x * 256 + threadIdx.x;   // o*4608 + t*512 + c
    const int c = idx & 511;
    const int rest = idx >> 9;
    const int t = rest % 9;
    const int o = rest / 9;
    const float v = conv_w[(size_t)o * KDIM_ + c * 9 + t];
    const __nv_bfloat16 h = __float2bfloat16_rn(v);
    g_wh[idx] = h;
    g_wl[idx] = __float2bfloat16_rn(v - __bfloat162float(h));
}

__global__ void prep_planes(const float* __restrict__ x) {
    const int idx = blockIdx.x * 256 + threadIdx.x;
    const int px = idx & 63;
    int rest = idx >> 6;
    const int y = rest % 66;
    rest /= 66;
    const int s = rest % 3;
    const int bc = rest / 3;
    const int xc = px + s - 1;
    float v = 0.f;
    if (y >= 1 && y <= 64 && xc >= 0 && xc < 64)
        v = x[((size_t)bc << 12) + ((y - 1) << 6) + xc] * g_style[bc];
    const __nv_bfloat16 h = __float2bfloat16_rn(v);
    g_bh[idx] = h;
    g_bl[idx] = __float2bfloat16_rn(v - __bfloat162float(h));
}

// ---------------- main GEMM ----------------
// grid (4 m, 64 n, 8 b), 256 threads = 8 warps (4M x 2N), warp tile 32x32.
// stage 24KB: A [128m][8u] swizzled u^(m&7) (hi u0-3, lo u4-7)  = 16KB
//             B [32k][16u] swizzled (u&8)|((u&7)^(k&7)) (hi u<8) =  8KB

#define NC 144
#define STAGE 24576

__device__ __forceinline__ void cpa16(uint32_t dst, const void* src) {
    asm volatile("cp.async.cg.shared.global [%0], [%1], 16;"
                 :: "r"(dst), "l"(src) : "memory");
}

__device__ __forceinline__ void ldsm4(uint32_t* r, uint32_t a) {
    asm volatile("ldmatrix.sync.aligned.m8n8.x4.shared.b16 {%0,%1,%2,%3}, [%4];"
                 : "=r"(r[0]), "=r"(r[1]), "=r"(r[2]), "=r"(r[3]) : "r"(a));
}

__device__ __forceinline__ void ldsm4t(uint32_t* r, uint32_t a) {
    asm volatile("ldmatrix.sync.aligned.m8n8.x4.trans.shared.b16 {%0,%1,%2,%3}, [%4];"
                 : "=r"(r[0]), "=r"(r[1]), "=r"(r[2]), "=r"(r[3]) : "r"(a));
}

__device__ __forceinline__ void mma16816(float* d, const uint32_t* a,
                                         uint32_t b0, uint32_t b1) {
    asm volatile(
        "mma.sync.aligned.m16n8k16.row.col.f32.bf16.bf16.f32 "
        "{%0,%1,%2,%3}, {%4,%5,%6,%7}, {%8,%9}, {%0,%1,%2,%3};"
        : "+f"(d[0]), "+f"(d[1]), "+f"(d[2]), "+f"(d[3])
        : "r"(a[0]), "r"(a[1]), "r"(a[2]), "r"(a[3]), "r"(b0), "r"(b1));
}

__global__ __launch_bounds__(256, 2)
void conv_mma(const float* __restrict__ noise, const float* __restrict__ nscale,
              const float* __restrict__ bias, float* __restrict__ out) {
    __shared__ __align__(16) char smem[2 * STAGE];     // 48KB static
    const uint32_t sbase = (uint32_t)__cvta_generic_to_shared(smem);
    const int tid = threadIdx.x;
    const int wid = tid >> 5;
    const int lane = tid & 31;
    const int wm = wid >> 1;           // 0..3  (m offset 32*wm)
    const int wn = wid & 1;            // 0..1  (n offset 32*wn)
    const int m0 = blockIdx.x * 128;
    const int n0 = blockIdx.y * 64;    // pixel offset (= 1 image row)
    const int py0 = blockIdx.y;        // image row
    const int b = blockIdx.z;

    float acc[2][4][4];
    #pragma unroll
    for (int i = 0; i < 2; ++i)
        #pragma unroll
        for (int j = 0; j < 4; ++j)
            #pragma unroll
            for (int e = 0; e < 4; ++e) acc[i][j][e] = 0.f;

    // ---- async stage loader ----
    auto issue = [&](int kc, int st) {
        const int t = kc >> 4;               // 0..8
        const int c0 = (kc & 15) << 5;       // 0..480
        const int r = t / 3, s = t - 3 * r;
        const uint32_t A0 = sbase + st * STAGE;
        const uint32_t B0 = A0 + 16384;
        // A: 1024 units of 16B
        #pragma unroll
        for (int i = 0; i < 4; ++i) {
            const int v = tid + (i << 8);
            const int m = v >> 3, u = v & 7;
            const __nv_bfloat16* src = (u < 4 ? g_wh : g_wl)
                + (size_t)(m0 + m) * KDIM_ + t * 512 + c0 + ((u & 3) << 3);
            cpa16(A0 + (m << 7) + ((u ^ (m & 7)) << 4), src);
        }
        // B: 512 units of 16B
        #pragma unroll
        for (int i = 0; i < 2; ++i) {
            const int v = tid + (i << 8);
            const int k = v >> 4, u = v & 15;
            const __nv_bfloat16* src = (u < 8 ? g_bh : g_bl)
                + ((((size_t)(b * 512 + c0 + k) * 3 + s) * 66) + (py0 + r)) * 64
                + ((u & 7) << 3);
            const uint32_t col = (u & 8) | ((u & 7) ^ (k & 7));
            cpa16(B0 + (k << 8) + (col << 4), src);
        }
    };

    issue(0, 0);
    asm volatile("cp.async.commit_group;" ::: "memory");

    const int mrow = wm * 32 + (lane & 15);
    const int krow_base = (lane & 7) + ((lane >> 3) & 1) * 8;

    for (int kc = 0; kc < NC; ++kc) {
        const int st = kc & 1;
        if (kc + 1 < NC) {
            issue(kc + 1, st ^ 1);
            asm volatile("cp.async.commit_group;" ::: "memory");
            asm volatile("cp.async.wait_group 1;" ::: "memory");
        } else {
            asm volatile("cp.async.wait_group 0;" ::: "memory");
        }
        __syncthreads();

        const uint32_t A0 = sbase + st * STAGE;
        const uint32_t B0 = A0 + 16384;

        #pragma unroll
        for (int kh = 0; kh < 2; ++kh) {
            uint32_t ah[2][4], al[2][4], bh[2][4], bl[2][4];
            const int uh = kh * 2 + (lane >> 4);       // A hi unit
            #pragma unroll
            for (int mf = 0; mf < 2; ++mf) {
                const int m = mrow + mf * 16;
                ldsm4(ah[mf], A0 + (m << 7) + ((uh ^ (m & 7)) << 4));
                ldsm4(al[mf], A0 + (m << 7) + (((uh + 4) ^ (m & 7)) << 4));
            }
            const int k = kh * 16 + krow_base;
            #pragma unroll
            for (int nb = 0; nb < 2; ++nb) {
                const int u = wn * 4 + nb * 2 + (lane >> 4);
                const uint32_t ch = (u & 7) ^ (k & 7);
                ldsm4t(bh[nb], B0 + (k << 8) + (ch << 4));
                const uint32_t cl = 8u | ((u & 7) ^ (k & 7));
                ldsm4t(bl[nb], B0 + (k << 8) + (cl << 4));
            }
            #pragma unroll
            for (int mf = 0; mf < 2; ++mf)
                #pragma unroll
                for (int nb = 0; nb < 2; ++nb)
                    #pragma unroll
                    for (int h = 0; h < 2; ++h) {
                        float* d = acc[mf][nb * 2 + h];
                        mma16816(d, ah[mf], bh[nb][h * 2], bh[nb][h * 2 + 1]);
                        mma16816(d, al[mf], bh[nb][h * 2], bh[nb][h * 2 + 1]);
                        mma16816(d, ah[mf], bl[nb][h * 2], bl[nb][h * 2 + 1]);
                    }
        }
        __syncthreads();
    }

    // ---- epilogue ----
    const float ns = nscale[0];
    const int lr = lane >> 2;
    const int lc = (lane & 3) * 2;
    const int nbase = n0 + wn * 32 + lc;
    float nz[4][2];
    #pragma unroll
    for (int n8 = 0; n8 < 4; ++n8) {
        nz[n8][0] = noise[b * NPIX_ + nbase + n8 * 8] * ns;
        nz[n8][1] = noise[b * NPIX_ + nbase + n8 * 8 + 1] * ns;
    }
    #pragma unroll
    for (int mf = 0; mf < 2; ++mf) {
        const int row0 = m0 + wm * 32 + mf * 16 + lr;
        const int row1 = row0 + 8;
        const float dc0 = g_dcoef[b * COUT_ + row0], bi0 = bias[row0];
        const float dc1 = g_dcoef[b * COUT_ + row1], bi1 = bias[row1];
        #pragma unroll
        for (int n8 = 0; n8 < 4; ++n8) {
            const int n = nbase + n8 * 8;
            const float* d = acc[mf][n8];
            float v0 = d[0] * dc0 + nz[n8][0] + bi0;
            float v1 = d[1] * dc0 + nz[n8][1] + bi0;
            float v2 = d[2] * dc1 + nz[n8][0] + bi1;
            float v3 = d[3] * dc1 + nz[n8][1] + bi1;
            v0 = (v0 > 0.f) ? v0 * LRELU_GAIN : v0 * (0.2f * LRELU_GAIN);
            v1 = (v1 > 0.f) ? v1 * LRELU_GAIN : v1 * (0.2f * LRELU_GAIN);
            v2 = (v2 > 0.f) ? v2 * LRELU_GAIN : v2 * (0.2f * LRELU_GAIN);
            v3 = (v3 > 0.f) ? v3 * LRELU_GAIN : v3 * (0.2f * LRELU_GAIN);
            float* o0 = out + ((size_t)(b * COUT_ + row0)) * NPIX_ + n;
            float* o1 = out + ((size_t)(b * COUT_ + row1)) * NPIX_ + n;
            *reinterpret_cast<float2*>(o0) = make_float2(v0, v1);
            *reinterpret_cast<float2*>(o1) = make_float2(v2, v3);
        }
    }
}

// ---------------- launch ----------------

extern "C" void kernel_launch(void* const* d_in, const int* in_sizes, int n_in,
                              void* d_out, int out_size) {
    (void)in_sizes; (void)n_in; (void)out_size;
    const float* x        = (const float*)d_in[0];
    const float* w        = (const float*)d_in[1];
    const float* noise    = (const float*)d_in[2];
    const float* affine_w = (const float*)d_in[3];
    const float* affine_b = (const float*)d_in[4];
    const float* conv_w   = (const float*)d_in[5];
    const float* nscale   = (const float*)d_in[6];
    const float* bias     = (const float*)d_in[7];
    float* out = (float*)d_out;

    prep_style<<<B_, SDIM_>>>(w, affine_w, affine_b);
    prep_wsq<<<(COUT_ * CIN_) / 256, 256>>>(conv_w);
    prep_dcoef<<<B_, COUT_>>>();
    prep_wsplit<<<(COUT_ * KDIM_) / 256, 256>>>(conv_w);
    prep_planes<<<(int)(PLANE_ELEMS / 256), 256>>>(x);

    conv_mma<<<dim3(4, 64, 8), 256>>>(noise, nscale, bias, out);
}

// round 7
// speedup vs baseline: 5.7095x; 1.8123x over previous
#include <cuda_runtime.h>
#include <cuda_fp16.h>
#include <cstdint>
#include <cstddef>

// ---------------------------------------------------------------------------
// StyleLayer via single-pass fp16 mma.sync (fp32 accum), static smem.
//   style  = w @ (affine_w*AFF_SCALE)^T + affine_b
//   dcoef  = CONV_SCALE * rsqrt(CONV_SCALE^2 * sum_c style^2*wsq + 1e-8)
//   planes: P[b][c][s][y][px] = pad(x*style)[b,c,y,px+s]   (fp16)
//   W[o][k'=t*512+c] = conv_w[o][c][t]                      (fp16)
//   D = W * P  (one pass), epilogue: *dcoef + noise*ns + bias -> lrelu*sqrt2
// GEMM per sample: M=512, N=4096, K=4608.
// CTA tile 128x128 (2 image rows), K-chunk 32, 2-stage cp.async,
// 8 warps (2M x 4N, warp 64x32). smem/stage: A 128x80B pad + B 32x256B swz.
// ---------------------------------------------------------------------------

#define B_      8
#define CIN_    512
#define COUT_   512
#define SDIM_   512
#define NPIX_   4096
#define KDIM_   4608
#define AFF_SCALE   0.044194173824159216f
#define CONV_SCALE  0.014731391274719739f
#define LRELU_GAIN  1.4142135623730951f

#define PLANE_ELEMS ((size_t)B_ * CIN_ * 3 * 66 * 64)
__device__ __align__(16) static __half g_pf[PLANE_ELEMS];
__device__ __align__(16) static __half g_wf[COUT_ * KDIM_];
__device__ static float g_style[B_ * CIN_];
__device__ static float g_wsq[COUT_ * CIN_];
__device__ static float g_dcoef[B_ * COUT_];

// ---------------- prep kernels ----------------

__global__ void prep_style(const float* __restrict__ w,
                           const float* __restrict__ affine_w,
                           const float* __restrict__ affine_b) {
    __shared__ float ws[SDIM_];
    const int b = blockIdx.x, c = threadIdx.x;
    ws[c] = w[b * SDIM_ + c];
    __syncthreads();
    const float* ar = affine_w + c * SDIM_;
    float s = 0.f;
    #pragma unroll 8
    for (int k = 0; k < SDIM_; ++k) s += ws[k] * ar[k];
    g_style[b * CIN_ + c] = s * AFF_SCALE + affine_b[c];
}

__global__ void prep_wsq(const float* __restrict__ conv_w) {
    const int idx = blockIdx.x * blockDim.x + threadIdx.x;
    if (idx >= COUT_ * CIN_) return;
    const float* p = conv_w + idx * 9;
    float s = 0.f;
    #pragma unroll
    for (int t = 0; t < 9; ++t) s += p[t] * p[t];
    g_wsq[idx] = s;
}

__global__ void prep_dcoef() {
    __shared__ float s2[CIN_];
    const int b = blockIdx.x, o = threadIdx.x;
    const float st = g_style[b * CIN_ + o];
    s2[o] = st * st;
    __syncthreads();
    const float* wr = g_wsq + o * CIN_;
    float s = 0.f;
    #pragma unroll 8
    for (int c = 0; c < CIN_; ++c) s += s2[c] * wr[c];
    g_dcoef[b * COUT_ + o] =
        CONV_SCALE * rsqrtf(CONV_SCALE * CONV_SCALE * s + 1e-8f);
}

__global__ void prep_wf(const float* __restrict__ conv_w) {
    const int idx = blockIdx.x * 256 + threadIdx.x;   // o*4608 + t*512 + c
    const int c = idx & 511;
    const int rest = idx >> 9;
    const int t = rest % 9;
    const int o = rest / 9;
    g_wf[idx] = __float2half_rn(conv_w[(size_t)o * KDIM_ + c * 9 + t]);
}

__global__ void prep_planes(const float* __restrict__ x) {
    const int idx = blockIdx.x * 256 + threadIdx.x;
    const int px = idx & 63;
    int rest = idx >> 6;
    const int y = rest % 66;
    rest /= 66;
    const int s = rest % 3;
    const int bc = rest / 3;
    const int xc = px + s - 1;
    float v = 0.f;
    if (y >= 1 && y <= 64 && xc >= 0 && xc < 64)
        v = x[((size_t)bc << 12) + ((y - 1) << 6) + xc] * g_style[bc];
    g_pf[idx] = __float2half_rn(v);
}

// ---------------- main GEMM ----------------
// grid (4 m, 32 n, 8 b), 256 threads = 8 warps (2M x 4N), warp tile 64x32.
// stage 18432B: A [128m][4u of 16B] row stride 80B (pad; conflict-free)
//               B [32k][16u] swizzled (u&8)|((u&7)^(k&7))

#define NC 144
#define ASTRIDE 80
#define ABYTES  (128 * ASTRIDE)     // 10240
#define STAGE   (ABYTES + 8192)     // 18432

__device__ __forceinline__ void cpa16(uint32_t dst, const void* src) {
    asm volatile("cp.async.cg.shared.global [%0], [%1], 16;"
                 :: "r"(dst), "l"(src) : "memory");
}

__device__ __forceinline__ void ldsm4(uint32_t* r, uint32_t a) {
    asm volatile("ldmatrix.sync.aligned.m8n8.x4.shared.b16 {%0,%1,%2,%3}, [%4];"
                 : "=r"(r[0]), "=r"(r[1]), "=r"(r[2]), "=r"(r[3]) : "r"(a));
}

__device__ __forceinline__ void ldsm4t(uint32_t* r, uint32_t a) {
    asm volatile("ldmatrix.sync.aligned.m8n8.x4.trans.shared.b16 {%0,%1,%2,%3}, [%4];"
                 : "=r"(r[0]), "=r"(r[1]), "=r"(r[2]), "=r"(r[3]) : "r"(a));
}

__device__ __forceinline__ void mma16816(float* d, const uint32_t* a,
                                         uint32_t b0, uint32_t b1) {
    asm volatile(
        "mma.sync.aligned.m16n8k16.row.col.f32.f16.f16.f32 "
        "{%0,%1,%2,%3}, {%4,%5,%6,%7}, {%8,%9}, {%0,%1,%2,%3};"
        : "+f"(d[0]), "+f"(d[1]), "+f"(d[2]), "+f"(d[3])
        : "r"(a[0]), "r"(a[1]), "r"(a[2]), "r"(a[3]), "r"(b0), "r"(b1));
}

__global__ __launch_bounds__(256, 2)
void conv_mma(const float* __restrict__ noise, const float* __restrict__ nscale,
              const float* __restrict__ bias, float* __restrict__ out) {
    __shared__ __align__(16) char smem[2 * STAGE];     // 36.9KB static
    const uint32_t sbase = (uint32_t)__cvta_generic_to_shared(smem);
    const int tid = threadIdx.x;
    const int wid = tid >> 5;
    const int lane = tid & 31;
    const int wm = wid >> 2;           // 0..1  (m offset 64*wm)
    const int wn = wid & 3;            // 0..3  (n offset 32*wn)
    const int m0 = blockIdx.x * 128;
    const int n0 = blockIdx.y * 128;   // pixel offset (= 2 image rows)
    const int py0 = blockIdx.y * 2;
    const int b = blockIdx.z;

    float acc[4][4][4];
    #pragma unroll
    for (int i = 0; i < 4; ++i)
        #pragma unroll
        for (int j = 0; j < 4; ++j)
            #pragma unroll
            for (int e = 0; e < 4; ++e) acc[i][j][e] = 0.f;

    // ---- async stage loader: 4 cp.async per thread ----
    auto issue = [&](int kc, int st) {
        const int t = kc >> 4;               // 0..8
        const int c0 = (kc & 15) << 5;       // 0..480
        const int r = t / 3, s = t - 3 * r;
        const uint32_t A0 = sbase + st * STAGE;
        const uint32_t B0 = A0 + ABYTES;
        // A: 512 units of 16B
        #pragma unroll
        for (int i = 0; i < 2; ++i) {
            const int v = tid + (i << 8);
            const int m = v >> 2, u = v & 3;
            const __half* src = g_wf + (size_t)(m0 + m) * KDIM_
                              + t * 512 + c0 + (u << 3);
            cpa16(A0 + m * ASTRIDE + (u << 4), src);
        }
        // B: 512 units of 16B (u<8: row py0, u>=8: row py0+1)
        #pragma unroll
        for (int i = 0; i < 2; ++i) {
            const int v = tid + (i << 8);
            const int k = v >> 4, u = v & 15;
            const __half* src = g_pf
                + ((((size_t)(b * 512 + c0 + k) * 3 + s) * 66)
                   + (py0 + (u >> 3) + r)) * 64 + ((u & 7) << 3);
            const uint32_t col = (u & 8) | ((u & 7) ^ (k & 7));
            cpa16(B0 + (k << 8) + (col << 4), src);
        }
    };

    issue(0, 0);
    asm volatile("cp.async.commit_group;" ::: "memory");

    const int mrow = wm * 64 + (lane & 15);
    const int krow_base = (lane & 7) + ((lane >> 3) & 1) * 8;

    for (int kc = 0; kc < NC; ++kc) {
        const int st = kc & 1;
        if (kc + 1 < NC) {
            issue(kc + 1, st ^ 1);
            asm volatile("cp.async.commit_group;" ::: "memory");
            asm volatile("cp.async.wait_group 1;" ::: "memory");
        } else {
            asm volatile("cp.async.wait_group 0;" ::: "memory");
        }
        __syncthreads();

        const uint32_t A0 = sbase + st * STAGE;
        const uint32_t B0 = A0 + ABYTES;

        #pragma unroll
        for (int kh = 0; kh < 2; ++kh) {
            uint32_t af[4][4], bf[2][4];
            const int ua = kh * 2 + (lane >> 4);       // A unit 0..3
            #pragma unroll
            for (int mf = 0; mf < 4; ++mf) {
                const int m = mrow + mf * 16;
                ldsm4(af[mf], A0 + m * ASTRIDE + (ua << 4));
            }
            const int k = kh * 16 + krow_base;
            #pragma unroll
            for (int nb = 0; nb < 2; ++nb) {
                const int u = wn * 4 + nb * 2 + (lane >> 4);
                const uint32_t col = (u & 8) | ((u & 7) ^ (k & 7));
                ldsm4t(bf[nb], B0 + (k << 8) + (col << 4));
            }
            #pragma unroll
            for (int mf = 0; mf < 4; ++mf)
                #pragma unroll
                for (int nb = 0; nb < 2; ++nb)
                    #pragma unroll
                    for (int h = 0; h < 2; ++h)
                        mma16816(acc[mf][nb * 2 + h], af[mf],
                                 bf[nb][h * 2], bf[nb][h * 2 + 1]);
        }
        __syncthreads();
    }

    // ---- epilogue ----
    const float ns = nscale[0];
    const int lr = lane >> 2;
    const int lc = (lane & 3) * 2;
    const int nbase = n0 + wn * 32 + lc;
    float nz[4][2];
    #pragma unroll
    for (int n8 = 0; n8 < 4; ++n8) {
        nz[n8][0] = noise[b * NPIX_ + nbase + n8 * 8] * ns;
        nz[n8][1] = noise[b * NPIX_ + nbase + n8 * 8 + 1] * ns;
    }
    #pragma unroll
    for (int mf = 0; mf < 4; ++mf) {
        const int row0 = m0 + wm * 64 + mf * 16 + lr;
        const int row1 = row0 + 8;
        const float dc0 = g_dcoef[b * COUT_ + row0], bi0 = bias[row0];
        const float dc1 = g_dcoef[b * COUT_ + row1], bi1 = bias[row1];
        #pragma unroll
        for (int n8 = 0; n8 < 4; ++n8) {
            const int n = nbase + n8 * 8;
            const float* d = acc[mf][n8];
            float v0 = d[0] * dc0 + nz[n8][0] + bi0;
            float v1 = d[1] * dc0 + nz[n8][1] + bi0;
            float v2 = d[2] * dc1 + nz[n8][0] + bi1;
            float v3 = d[3] * dc1 + nz[n8][1] + bi1;
            v0 = (v0 > 0.f) ? v0 * LRELU_GAIN : v0 * (0.2f * LRELU_GAIN);
            v1 = (v1 > 0.f) ? v1 * LRELU_GAIN : v1 * (0.2f * LRELU_GAIN);
            v2 = (v2 > 0.f) ? v2 * LRELU_GAIN : v2 * (0.2f * LRELU_GAIN);
            v3 = (v3 > 0.f) ? v3 * LRELU_GAIN : v3 * (0.2f * LRELU_GAIN);
            float* o0 = out + ((size_t)(b * COUT_ + row0)) * NPIX_ + n;
            float* o1 = out + ((size_t)(b * COUT_ + row1)) * NPIX_ + n;
            *reinterpret_cast<float2*>(o0) = make_float2(v0, v1);
            *reinterpret_cast<float2*>(o1) = make_float2(v2, v3);
        }
    }
}

// ---------------- launch ----------------

extern "C" void kernel_launch(void* const* d_in, const int* in_sizes, int n_in,
                              void* d_out, int out_size) {
    (void)in_sizes; (void)n_in; (void)out_size;
    const float* x        = (const float*)d_in[0];
    const float* w        = (const float*)d_in[1];
    const float* noise    = (const float*)d_in[2];
    const float* affine_w = (const float*)d_in[3];
    const float* affine_b = (const float*)d_in[4];
    const float* conv_w   = (const float*)d_in[5];
    const float* nscale   = (const float*)d_in[6];
    const float* bias     = (const float*)d_in[7];
    float* out = (float*)d_out;

    prep_style<<<B_, SDIM_>>>(w, affine_w, affine_b);
    prep_wsq<<<(COUT_ * CIN_) / 256, 256>>>(conv_w);
    prep_dcoef<<<B_, COUT_>>>();
    prep_wf<<<(COUT_ * KDIM_) / 256, 256>>>(conv_w);
    prep_planes<<<(int)(PLANE_ELEMS / 256), 256>>>(x);

    conv_mma<<<dim3(4, 32, 8), 256>>>(noise, nscale, bias, out);
}

// round 10
// speedup vs baseline: 5.9964x; 1.0503x over previous
#include <cuda_runtime.h>
#include <cuda_fp16.h>
#include <cstdint>
#include <cstddef>

// ---------------------------------------------------------------------------
// StyleLayer via single-pass fp16 mma.sync (fp32 accum), static 48KB smem.
//   style  = w @ (affine_w*AFF_SCALE)^T + affine_b
//   dcoef  = CONV_SCALE * rsqrt(CONV_SCALE^2 * sum_c style^2*wsq + 1e-8)
//   planes: P[b][c][s][y][px] = pad(x*style)[b,c,y,px+s]   (fp16)
//   WT[k'=t*512+c][o] = conv_w[o][c][t]                     (fp16, K-major)
//   D = W * P, epilogue: *dcoef + noise*ns + bias -> lrelu*sqrt2
// GEMM per sample: M=512, N=4096, K=4608.
// CTA 128x128, K-chunk 32, 3-stage cp.async (1 sync/chunk), 4 warps
// (2M x 2N, warp 64x64), occ 2. Both A and B K-major in smem, ldsm.trans.
// ---------------------------------------------------------------------------

#define B_      8
#define CIN_    512
#define COUT_   512
#define SDIM_   512
#define NPIX_   4096
#define KDIM_   4608
#define AFF_SCALE   0.044194173824159216f
#define CONV_SCALE  0.014731391274719739f
#define LRELU_GAIN  1.4142135623730951f

#define PLANE_ELEMS ((size_t)B_ * CIN_ * 3 * 66 * 64)
__device__ __align__(16) static __half g_pf[PLANE_ELEMS];
__device__ __align__(16) static __half g_wfT[KDIM_ * COUT_];   // [k'][o]
__device__ static float g_style[B_ * CIN_];
__device__ static float g_wsq[COUT_ * CIN_];
__device__ static float g_dcoef[B_ * COUT_];

// ---------------- prep kernels ----------------

__global__ void prep_style(const float* __restrict__ w,
                           const float* __restrict__ affine_w,
                           const float* __restrict__ affine_b) {
    __shared__ float ws[SDIM_];
    const int b = blockIdx.x, c = threadIdx.x;
    ws[c] = w[b * SDIM_ + c];
    __syncthreads();
    const float* ar = affine_w + c * SDIM_;
    float s = 0.f;
    #pragma unroll 8
    for (int k = 0; k < SDIM_; ++k) s += ws[k] * ar[k];
    g_style[b * CIN_ + c] = s * AFF_SCALE + affine_b[c];
}

__global__ void prep_wsq(const float* __restrict__ conv_w) {
    const int idx = blockIdx.x * blockDim.x + threadIdx.x;
    if (idx >= COUT_ * CIN_) return;
    const float* p = conv_w + idx * 9;
    float s = 0.f;
    #pragma unroll
    for (int t = 0; t < 9; ++t) s += p[t] * p[t];
    g_wsq[idx] = s;
}

__global__ void prep_dcoef() {
    __shared__ float s2[CIN_];
    const int b = blockIdx.x, o = threadIdx.x;
    const float st = g_style[b * CIN_ + o];
    s2[o] = st * st;
    __syncthreads();
    const float* wr = g_wsq + o * CIN_;
    float s = 0.f;
    #pragma unroll 8
    for (int c = 0; c < CIN_; ++c) s += s2[c] * wr[c];
    g_dcoef[b * COUT_ + o] =
        CONV_SCALE * rsqrtf(CONV_SCALE * CONV_SCALE * s + 1e-8f);
}

// g_wfT[(t*512+c)*512 + o] = conv_w[o][c][t]  (coalesced writes)
__global__ void prep_wfT(const float* __restrict__ conv_w) {
    const int idx = blockIdx.x * 256 + threadIdx.x;   // k'*512 + o
    const int o = idx & 511;
    const int kp = idx >> 9;
    const int t = kp >> 9;
    const int c = kp & 511;
    g_wfT[idx] = __float2half_rn(conv_w[(size_t)o * KDIM_ + c * 9 + t]);
}

__global__ void prep_planes(const float* __restrict__ x) {
    const int idx = blockIdx.x * 256 + threadIdx.x;
    const int px = idx & 63;
    int rest = idx >> 6;
    const int y = rest % 66;
    rest /= 66;
    const int s = rest % 3;
    const int bc = rest / 3;
    const int xc = px + s - 1;
    float v = 0.f;
    if (y >= 1 && y <= 64 && xc >= 0 && xc < 64)
        v = x[((size_t)bc << 12) + ((y - 1) << 6) + xc] * g_style[bc];
    g_pf[idx] = __float2half_rn(v);
}

// ---------------- main GEMM ----------------
// grid (4 m, 32 n, 8 b), 128 threads = 4 warps (2M x 2N), warp tile 64x64.
// stage 16KB: A [32k][16u of 16B] (K-major, 256B rows) swizzled
//             B [32k][16u of 16B] (256B rows) swizzled; col=(u&~7)|((u&7)^(k&7))
// 3 stages = 48KB static.

#define NC 144
#define ABYTES 8192
#define STAGE  16384

__device__ __forceinline__ void cpa16(uint32_t dst, const void* src) {
    asm volatile("cp.async.cg.shared.global [%0], [%1], 16;"
                 :: "r"(dst), "l"(src) : "memory");
}

__device__ __forceinline__ void ldsm4t(uint32_t* r, uint32_t a) {
    asm volatile("ldmatrix.sync.aligned.m8n8.x4.trans.shared.b16 {%0,%1,%2,%3}, [%4];"
                 : "=r"(r[0]), "=r"(r[1]), "=r"(r[2]), "=r"(r[3]) : "r"(a));
}

__device__ __forceinline__ void mma16816(float* d, const uint32_t* a,
                                         uint32_t b0, uint32_t b1) {
    asm volatile(
        "mma.sync.aligned.m16n8k16.row.col.f32.f16.f16.f32 "
        "{%0,%1,%2,%3}, {%4,%5,%6,%7}, {%8,%9}, {%0,%1,%2,%3};"
        : "+f"(d[0]), "+f"(d[1]), "+f"(d[2]), "+f"(d[3])
        : "r"(a[0]), "r"(a[1]), "r"(a[2]), "r"(a[3]), "r"(b0), "r"(b1));
}

__global__ __launch_bounds__(128, 2)
void conv_mma(const float* __restrict__ noise, const float* __restrict__ nscale,
              const float* __restrict__ bias, float* __restrict__ out) {
    __shared__ __align__(16) char smem[3 * STAGE];    // 48KB static
    const uint32_t sbase = (uint32_t)__cvta_generic_to_shared(smem);
    const int tid = threadIdx.x;
    const int wid = tid >> 5;
    const int lane = tid & 31;
    const int wm = wid >> 1;           // 0..1  (m offset 64*wm)
    const int wn = wid & 1;            // 0..1  (n offset 64*wn)
    const int m0 = blockIdx.x * 128;
    const int n0 = blockIdx.y * 128;   // pixel offset (= 2 image rows)
    const int py0 = blockIdx.y * 2;
    const int b = blockIdx.z;

    float acc[4][8][4];
    #pragma unroll
    for (int i = 0; i < 4; ++i)
        #pragma unroll
        for (int j = 0; j < 8; ++j)
            #pragma unroll
            for (int e = 0; e < 4; ++e) acc[i][j][e] = 0.f;

    // ---- async stage loader: 8 cp.async per thread ----
    auto issue = [&](int kc) {
        const int st = kc % 3;
        const int t = kc >> 4;               // 0..8
        const int c0 = (kc & 15) << 5;       // 0..480
        const int r = t / 3, s = t - 3 * r;
        const uint32_t A0 = sbase + st * STAGE;
        const uint32_t B0 = A0 + ABYTES;
        // A: 512 units of 16B; unit (k,u) = WT[t*512+c0+k][m0 + u*8 .. +8]
        #pragma unroll
        for (int i = 0; i < 4; ++i) {
            const int v = tid + (i << 7);
            const int k = v >> 4, u = v & 15;
            const __half* src = g_wfT + (size_t)(t * 512 + c0 + k) * COUT_
                              + m0 + (u << 3);
            const uint32_t col = (u & ~7) | ((u & 7) ^ (k & 7));
            cpa16(A0 + (k << 8) + (col << 4), src);
        }
        // B: 512 units of 16B; unit u -> pixel n = u*8 (py = u>>3, px=(u&7)*8)
        #pragma unroll
        for (int i = 0; i < 4; ++i) {
            const int v = tid + (i << 7);
            const int k = v >> 4, u = v & 15;
            const __half* src = g_pf
                + ((((size_t)(b * 512 + c0 + k) * 3 + s) * 66)
                   + (py0 + (u >> 3) + r)) * 64 + ((u & 7) << 3);
            const uint32_t col = (u & ~7) | ((u & 7) ^ (k & 7));
            cpa16(B0 + (k << 8) + (col << 4), src);
        }
        asm volatile("cp.async.commit_group;" ::: "memory");
    };

    issue(0);
    issue(1);

    // A (trans): m-half from lane bit3, k-half from lane bit4
    const int akrow = (lane & 7) + ((lane >> 4) & 1) * 8;
    const int auoff = (lane >> 3) & 1;
    // B (trans): k-half from lane bit3, u from lane bit4
    const int bkrow = (lane & 7) + ((lane >> 3) & 1) * 8;

    for (int kc = 0; kc < NC; ++kc) {
        if (kc == NC - 1)
            asm volatile("cp.async.wait_group 0;" ::: "memory");
        else
            asm volatile("cp.async.wait_group 1;" ::: "memory");
        __syncthreads();

        if (kc + 2 < NC) issue(kc + 2);

        const uint32_t A0 = sbase + (kc % 3) * STAGE;
        const uint32_t B0 = A0 + ABYTES;

        #pragma unroll
        for (int kh = 0; kh < 2; ++kh) {
            uint32_t af[4][4], bf[4][4];
            const int ka = kh * 16 + akrow;
            #pragma unroll
            for (int mf = 0; mf < 4; ++mf) {
                const int u = wm * 8 + mf * 2 + auoff;
                const uint32_t col = (u & ~7) | ((u & 7) ^ (ka & 7));
                ldsm4t(af[mf], A0 + (ka << 8) + (col << 4));
            }
            const int kb = kh * 16 + bkrow;
            #pragma unroll
            for (int nb = 0; nb < 4; ++nb) {
                const int u = wn * 8 + nb * 2 + (lane >> 4);
                const uint32_t col = (u & ~7) | ((u & 7) ^ (kb & 7));
                ldsm4t(bf[nb], B0 + (kb << 8) + (col << 4));
            }
            #pragma unroll
            for (int mf = 0; mf < 4; ++mf)
                #pragma unroll
                for (int nb = 0; nb < 4; ++nb)
                    #pragma unroll
                    for (int h = 0; h < 2; ++h)
                        mma16816(acc[mf][nb * 2 + h], af[mf],
                                 bf[nb][h * 2], bf[nb][h * 2 + 1]);
        }
    }

    // ---- epilogue ----
    const float ns = nscale[0];
    const int lr = lane >> 2;
    const int lc = (lane & 3) * 2;
    const int nbase = n0 + wn * 64 + lc;
    float nz[8][2];
    #pragma unroll
    for (int n8 = 0; n8 < 8; ++n8) {
        nz[n8][0] = noise[b * NPIX_ + nbase + n8 * 8] * ns;
        nz[n8][1] = noise[b * NPIX_ + nbase + n8 * 8 + 1] * ns;
    }
    #pragma unroll
    for (int mf = 0; mf < 4; ++mf) {
        const int row0 = m0 + wm * 64 + mf * 16 + lr;
        const int row1 = row0 + 8;
        const float dc0 = g_dcoef[b * COUT_ + row0], bi0 = bias[row0];
        const float dc1 = g_dcoef[b * COUT_ + row1], bi1 = bias[row1];
        #pragma unroll
        for (int n8 = 0; n8 < 8; ++n8) {
            const int n = nbase + n8 * 8;
            const float* d = acc[mf][n8];
            float v0 = d[0] * dc0 + nz[n8][0] + bi0;
            float v1 = d[1] * dc0 + nz[n8][1] + bi0;
            float v2 = d[2] * dc1 + nz[n8][0] + bi1;
            float v3 = d[3] * dc1 + nz[n8][1] + bi1;
            v0 = (v0 > 0.f) ? v0 * LRELU_GAIN : v0 * (0.2f * LRELU_GAIN);
            v1 = (v1 > 0.f) ? v1 * LRELU_GAIN : v1 * (0.2f * LRELU_GAIN);
            v2 = (v2 > 0.f) ? v2 * LRELU_GAIN : v2 * (0.2f * LRELU_GAIN);
            v3 = (v3 > 0.f) ? v3 * LRELU_GAIN : v3 * (0.2f * LRELU_GAIN);
            float* o0 = out + ((size_t)(b * COUT_ + row0)) * NPIX_ + n;
            float* o1 = out + ((size_t)(b * COUT_ + row1)) * NPIX_ + n;
            *reinterpret_cast<float2*>(o0) = make_float2(v0, v1);
            *reinterpret_cast<float2*>(o1) = make_float2(v2, v3);
        }
    }
}

// ---------------- launch ----------------

extern "C" void kernel_launch(void* const* d_in, const int* in_sizes, int n_in,
                              void* d_out, int out_size) {
    (void)in_sizes; (void)n_in; (void)out_size;
    const float* x        = (const float*)d_in[0];
    const float* w        = (const float*)d_in[1];
    const float* noise    = (const float*)d_in[2];
    const float* affine_w = (const float*)d_in[3];
    const float* affine_b = (const float*)d_in[4];
    const float* conv_w   = (const float*)d_in[5];
    const float* nscale   = (const float*)d_in[6];
    const float* bias     = (const float*)d_in[7];
    float* out = (float*)d_out;

    prep_style<<<B_, SDIM_>>>(w, affine_w, affine_b);
    prep_wsq<<<(COUT_ * CIN_) / 256, 256>>>(conv_w);
    prep_dcoef<<<B_, COUT_>>>();
    prep_wfT<<<(KDIM_ * COUT_) / 256, 256>>>(conv_w);
    prep_planes<<<(int)(PLANE_ELEMS / 256), 256>>>(x);

    conv_mma<<<dim3(4, 32, 8), 128>>>(noise, nscale, bias, out);
}